// round 8
// baseline (speedup 1.0000x reference)
#include <cuda_runtime.h>
#include <cuda_bf16.h>
#include <cstdint>

// ============================================================================
// BilinearDiscriminator: out = sigmoid( (x @ W^T) @ y^T )
//   x: [16384, 128] f32, y: [16384, 128] f32, W: [128, 128] f32
//   out: [16384, 16384] f32
//
// Tensor path: mma.sync m16n8k16 bf16 (family-portable; tcgen05 is not
// available through this harness's compute_103 PTX build).
//
// Numerics: fp32 v split as v = hi + lo (both bf16, lo = bf16(v - hi)).
// Score computed as  hi_a.hi_b + hi_a.lo_b + lo_a.hi_b  (lo.lo dropped,
// ~2^-18 relative) -> ~fp32-grade scores, rel err ~1e-4 absolute on scores.
// This is 24 k-steps of 16 (K=384 equivalent) but SMEM keeps the compact
// K=256 [hi|lo] layout; the mainloop remaps (ka, kb) block pairs.
// ============================================================================

#define NROWS 16384
#define DDIM  128

static __device__ __align__(16) __nv_bfloat16 g_A[NROWS * 256];
static __device__ __align__(16) __nv_bfloat16 g_B[NROWS * 256];

// ---------------------------------------------------------------------------
// prep_x: Xt = x @ W^T (fp32), split into (hi, lo) bf16 -> g_A[n][0:128|128:256]
// ---------------------------------------------------------------------------
__global__ void __launch_bounds__(128, 1)
prep_x_kernel(const float* __restrict__ x, const float* __restrict__ W) {
    __shared__ float Xs[32][128];
    const int tid = threadIdx.x;          // output column d
    const int rowbase = blockIdx.x * 32;

    for (int i = tid; i < 32 * 128; i += 128)
        Xs[i >> 7][i & 127] = x[rowbase * 128 + i];

    float w[128];
    const float4* Wv = reinterpret_cast<const float4*>(W + tid * 128);
#pragma unroll
    for (int k = 0; k < 32; k++) {
        float4 v = Wv[k];
        w[4 * k + 0] = v.x; w[4 * k + 1] = v.y;
        w[4 * k + 2] = v.z; w[4 * k + 3] = v.w;
    }
    __syncthreads();

    for (int r = 0; r < 32; r++) {
        float a0 = 0.f, a1 = 0.f, a2 = 0.f, a3 = 0.f;
#pragma unroll
        for (int k = 0; k < 128; k += 4) {
            a0 += w[k + 0] * Xs[r][k + 0];
            a1 += w[k + 1] * Xs[r][k + 1];
            a2 += w[k + 2] * Xs[r][k + 2];
            a3 += w[k + 3] * Xs[r][k + 3];
        }
        float v = (a0 + a1) + (a2 + a3);
        __nv_bfloat16 hi = __float2bfloat16(v);
        __nv_bfloat16 lo = __float2bfloat16(v - __bfloat162float(hi));
        int grow = rowbase + r;
        g_A[grow * 256 + tid] = hi;
        g_A[grow * 256 + 128 + tid] = lo;
    }
}

// ---------------------------------------------------------------------------
// prep_y: split y fp32 -> (hi, lo) bf16 into g_B
// ---------------------------------------------------------------------------
__global__ void __launch_bounds__(256)
prep_y_kernel(const float* __restrict__ y, int total) {
    int i = blockIdx.x * blockDim.x + threadIdx.x;
    if (i >= total) return;
    float v = y[i];
    __nv_bfloat16 hi = __float2bfloat16(v);
    __nv_bfloat16 lo = __float2bfloat16(v - __bfloat162float(hi));
    int row = i >> 7, d = i & 127;
    g_B[row * 256 + d] = hi;
    g_B[row * 256 + 128 + d] = lo;
}

// ---------------------------------------------------------------------------
// GEMM + sigmoid via mma.sync m16n8k16 bf16.
//   CTA tile: 128(M) x 128(N), K=256 resident in SMEM (hi block + lo block).
//   8 warps: warp_m = wid&3 (32 rows), warp_n = wid>>2 (64 cols).
//   SMEM per operand: 128 rows x 512B (32 x 16B chunks), chunk swizzle
//   phys_c = c ^ (row & 7)  -> conflict-free STS fill and ldmatrix phases.
//   Mainloop: for q = 0..7 (k-steps of 16 within the 128-elem hi/lo blocks),
//   load fragments A_hi, A_lo, B_hi, B_lo once and issue the 3 MMA groups
//   hi.hi, hi.lo, lo.hi.
// ---------------------------------------------------------------------------
static constexpr int SMEM_TILE  = 128 * 512;       // 64 KB per operand
static constexpr int SMEM_TOTAL = 2 * SMEM_TILE;   // 128 KB

__device__ __forceinline__ uint32_t smem_u32(const void* p) {
    uint32_t a;
    asm("{ .reg .u64 t; cvta.to.shared.u64 t, %1; cvt.u32.u64 %0, t; }"
        : "=r"(a) : "l"(p));
    return a;
}

__device__ __forceinline__ void ldsm_x4(uint32_t addr, uint32_t& d0, uint32_t& d1,
                                        uint32_t& d2, uint32_t& d3) {
    asm volatile("ldmatrix.sync.aligned.m8n8.x4.shared.b16 {%0,%1,%2,%3}, [%4];"
                 : "=r"(d0), "=r"(d1), "=r"(d2), "=r"(d3) : "r"(addr));
}

__device__ __forceinline__ void mma_16816(float& c0, float& c1, float& c2, float& c3,
                                          uint32_t a0, uint32_t a1, uint32_t a2, uint32_t a3,
                                          uint32_t b0, uint32_t b1) {
    asm volatile("mma.sync.aligned.m16n8k16.row.col.f32.bf16.bf16.f32 "
                 "{%0,%1,%2,%3}, {%4,%5,%6,%7}, {%8,%9}, {%0,%1,%2,%3};"
                 : "+f"(c0), "+f"(c1), "+f"(c2), "+f"(c3)
                 : "r"(a0), "r"(a1), "r"(a2), "r"(a3), "r"(b0), "r"(b1));
}

__device__ __forceinline__ float sigmoidf_fast(float x) {
    float e = __expf(-x);
    return __fdividef(1.0f, 1.0f + e);
}

__global__ void __launch_bounds__(256, 1)
gemm_sigmoid_kernel(float* __restrict__ out, int mtot) {
    extern __shared__ char smem[];
    const uint32_t sA = smem_u32(smem);
    const uint32_t sB = sA + SMEM_TILE;
    const int tid = threadIdx.x;
    const int wid = tid >> 5;
    const int lid = tid & 31;
    const int warp_m = wid & 3;    // 4 warps along M, 32 rows each
    const int warp_n = wid >> 2;   // 2 warps along N, 64 cols each

    const int arowbase = blockIdx.y * 128;   // output rows  (x rows)
    const int browbase = blockIdx.x * 128;   // output cols  (y rows)

    // ---- Fill SMEM: 128 rows x 32 chunks of 16B, per operand ----
    const uint4* gA = reinterpret_cast<const uint4*>(g_A) + (size_t)arowbase * 32;
    const uint4* gB = reinterpret_cast<const uint4*>(g_B) + (size_t)browbase * 32;
#pragma unroll
    for (int idx = tid; idx < 4096; idx += 256) {
        int row = idx >> 5;
        int c   = idx & 31;
        uint32_t off = (uint32_t)row * 512u + (uint32_t)((c ^ (row & 7)) << 4);
        *reinterpret_cast<uint4*>(smem + off)             = gA[idx];
        *reinterpret_cast<uint4*>(smem + SMEM_TILE + off) = gB[idx];
    }
    __syncthreads();

    // ---- Mainloop ----
    float acc[2][8][4];
#pragma unroll
    for (int i = 0; i < 2; i++)
#pragma unroll
        for (int j = 0; j < 8; j++)
#pragma unroll
            for (int q = 0; q < 4; q++) acc[i][j][q] = 0.f;

    const int lane_lo = lid & 15;   // row within 16-row ldmatrix block
    const int lane_hi = lid >> 4;   // 0/1: 16B chunk-half select

    const int a_row0 = warp_m * 32 + lane_lo;        // + i*16
    const int b_row0 = warp_n * 64 + lane_lo;        // + jb*16

#pragma unroll
    for (int q = 0; q < 8; q++) {
        // chunk indices: hi block = chunks [0,16), lo block = chunks [16,32)
        const int ch_hi = q * 2 + lane_hi;
        const int ch_lo = 16 + q * 2 + lane_hi;

        uint32_t a_hi[2][4], a_lo[2][4];
#pragma unroll
        for (int i = 0; i < 2; i++) {
            int row = a_row0 + i * 16;
            uint32_t base = sA + (uint32_t)row * 512u;
            ldsm_x4(base + (uint32_t)((ch_hi ^ (row & 7)) << 4),
                    a_hi[i][0], a_hi[i][1], a_hi[i][2], a_hi[i][3]);
            ldsm_x4(base + (uint32_t)((ch_lo ^ (row & 7)) << 4),
                    a_lo[i][0], a_lo[i][1], a_lo[i][2], a_lo[i][3]);
        }

        uint32_t b_hi[4][4], b_lo[4][4];
#pragma unroll
        for (int jb = 0; jb < 4; jb++) {
            int row = b_row0 + jb * 16;
            uint32_t base = sB + (uint32_t)row * 512u;
            ldsm_x4(base + (uint32_t)((ch_hi ^ (row & 7)) << 4),
                    b_hi[jb][0], b_hi[jb][1], b_hi[jb][2], b_hi[jb][3]);
            ldsm_x4(base + (uint32_t)((ch_lo ^ (row & 7)) << 4),
                    b_lo[jb][0], b_lo[jb][1], b_lo[jb][2], b_lo[jb][3]);
        }

        // Three product groups: hi.hi + hi.lo + lo.hi
#pragma unroll
        for (int i = 0; i < 2; i++)
#pragma unroll
            for (int j = 0; j < 8; j++) {
                int jb = j >> 1, sel = j & 1;
                mma_16816(acc[i][j][0], acc[i][j][1], acc[i][j][2], acc[i][j][3],
                          a_hi[i][0], a_hi[i][1], a_hi[i][2], a_hi[i][3],
                          b_hi[jb][sel], b_hi[jb][sel + 2]);
                mma_16816(acc[i][j][0], acc[i][j][1], acc[i][j][2], acc[i][j][3],
                          a_hi[i][0], a_hi[i][1], a_hi[i][2], a_hi[i][3],
                          b_lo[jb][sel], b_lo[jb][sel + 2]);
                mma_16816(acc[i][j][0], acc[i][j][1], acc[i][j][2], acc[i][j][3],
                          a_lo[i][0], a_lo[i][1], a_lo[i][2], a_lo[i][3],
                          b_hi[jb][sel], b_hi[jb][sel + 2]);
            }
    }

    // ---- Epilogue: sigmoid + coalesced float2 stores ----
    const int r_base = arowbase + warp_m * 32 + (lid >> 2);
    const int c_base = browbase + warp_n * 64 + ((lid & 3) << 1);
#pragma unroll
    for (int i = 0; i < 2; i++) {
        const int r0 = r_base + i * 16;
        float* p0 = out + (size_t)r0 * mtot + c_base;
        float* p1 = out + (size_t)(r0 + 8) * mtot + c_base;
#pragma unroll
        for (int j = 0; j < 8; j++) {
            float2 v0, v1;
            v0.x = sigmoidf_fast(acc[i][j][0]);
            v0.y = sigmoidf_fast(acc[i][j][1]);
            v1.x = sigmoidf_fast(acc[i][j][2]);
            v1.y = sigmoidf_fast(acc[i][j][3]);
            *reinterpret_cast<float2*>(p0 + j * 8) = v0;
            *reinterpret_cast<float2*>(p1 + j * 8) = v1;
        }
    }
}

// ---------------------------------------------------------------------------
// kernel_launch
// ---------------------------------------------------------------------------
extern "C" void kernel_launch(void* const* d_in, const int* in_sizes, int n_in,
                              void* d_out, int out_size) {
    const float* x = (const float*)d_in[0];   // [N, 128]
    const float* y = (const float*)d_in[1];   // [M, 128]
    const float* W = (const float*)d_in[2];   // [128, 128]
    float* out = (float*)d_out;

    const int N = in_sizes[0] / DDIM;   // 16384
    const int M = in_sizes[1] / DDIM;   // 16384

    cudaFuncSetAttribute(gemm_sigmoid_kernel,
                         cudaFuncAttributeMaxDynamicSharedMemorySize, SMEM_TOTAL);

    prep_x_kernel<<<N / 32, 128>>>(x, W);
    prep_y_kernel<<<(in_sizes[1] + 255) / 256, 256>>>(y, in_sizes[1]);

    dim3 grid(M / 128, N / 128);
    gemm_sigmoid_kernel<<<grid, 256, SMEM_TOTAL>>>(out, M);
}

// round 9
// speedup vs baseline: 2.3057x; 2.3057x over previous
#include <cuda_runtime.h>
#include <cuda_fp16.h>
#include <cstdint>

// ============================================================================
// BilinearDiscriminator: out = sigmoid( (x @ W^T) @ y^T )
//   x: [16384, 128] f32, y: [16384, 128] f32, W: [128, 128] f32
//   out: [16384, 16384] f32
//
// R9: single-product fp16 GEMM (K=128) on mma.sync m16n8k16.
// Precision anchor: bf16 single product measured rel_err = 2.945e-3 (R4).
// fp16 mantissa = +3 bits = 8x smaller operand rounding -> predicted ~3.7e-4,
// under the 1e-3 threshold with ~2.7x margin, at 1/3 of the tensor FLOPs of
// the 3-product bf16 scheme (which measured 823us, mma.sync-roofline-bound).
// ============================================================================

#define NROWS 16384
#define DDIM  128

static __device__ __align__(16) __half g_A[NROWS * DDIM];
static __device__ __align__(16) __half g_B[NROWS * DDIM];

// ---------------------------------------------------------------------------
// prep_x: Xt = x @ W^T in fp32, round to fp16 -> g_A
// ---------------------------------------------------------------------------
__global__ void __launch_bounds__(128, 1)
prep_x_kernel(const float* __restrict__ x, const float* __restrict__ W) {
    __shared__ float Xs[32][128];
    const int tid = threadIdx.x;          // output column d
    const int rowbase = blockIdx.x * 32;

    for (int i = tid; i < 32 * 128; i += 128)
        Xs[i >> 7][i & 127] = x[rowbase * 128 + i];

    float w[128];
    const float4* Wv = reinterpret_cast<const float4*>(W + tid * 128);
#pragma unroll
    for (int k = 0; k < 32; k++) {
        float4 v = Wv[k];
        w[4 * k + 0] = v.x; w[4 * k + 1] = v.y;
        w[4 * k + 2] = v.z; w[4 * k + 3] = v.w;
    }
    __syncthreads();

    for (int r = 0; r < 32; r++) {
        float a0 = 0.f, a1 = 0.f, a2 = 0.f, a3 = 0.f;
#pragma unroll
        for (int k = 0; k < 128; k += 4) {
            a0 += w[k + 0] * Xs[r][k + 0];
            a1 += w[k + 1] * Xs[r][k + 1];
            a2 += w[k + 2] * Xs[r][k + 2];
            a3 += w[k + 3] * Xs[r][k + 3];
        }
        float v = (a0 + a1) + (a2 + a3);
        g_A[(rowbase + r) * 128 + tid] = __float2half(v);
    }
}

// ---------------------------------------------------------------------------
// prep_y: y fp32 -> fp16 (vectorized 2 elems/thread)
// ---------------------------------------------------------------------------
__global__ void __launch_bounds__(256)
prep_y_kernel(const float* __restrict__ y, int total2) {
    int i = blockIdx.x * blockDim.x + threadIdx.x;
    if (i >= total2) return;
    float2 v = reinterpret_cast<const float2*>(y)[i];
    __half2 h = __floats2half2_rn(v.x, v.y);
    reinterpret_cast<__half2*>(g_B)[i] = h;
}

// ---------------------------------------------------------------------------
// GEMM + sigmoid via mma.sync m16n8k16 fp16, K=128.
//   CTA tile: 128(M) x 128(N). 8 warps: warp_m = wid&3, warp_n = wid>>2.
//   SMEM per operand: 128 rows x 256B (16 x 16B chunks), chunk swizzle
//   phys_c = c ^ (row & 7) -> conflict-free STS and ldmatrix phases.
//   2 CTAs/SM (64 KB smem total) so load/epilogue of one CTA overlaps the
//   MMA phase of the other.
// ---------------------------------------------------------------------------
static constexpr int SMEM_TILE  = 128 * 256;       // 32 KB per operand
static constexpr int SMEM_TOTAL = 2 * SMEM_TILE;   // 64 KB

__device__ __forceinline__ uint32_t smem_u32(const void* p) {
    uint32_t a;
    asm("{ .reg .u64 t; cvta.to.shared.u64 t, %1; cvt.u32.u64 %0, t; }"
        : "=r"(a) : "l"(p));
    return a;
}

__device__ __forceinline__ void ldsm_x4(uint32_t addr, uint32_t& d0, uint32_t& d1,
                                        uint32_t& d2, uint32_t& d3) {
    asm volatile("ldmatrix.sync.aligned.m8n8.x4.shared.b16 {%0,%1,%2,%3}, [%4];"
                 : "=r"(d0), "=r"(d1), "=r"(d2), "=r"(d3) : "r"(addr));
}

__device__ __forceinline__ void mma_16816(float& c0, float& c1, float& c2, float& c3,
                                          uint32_t a0, uint32_t a1, uint32_t a2, uint32_t a3,
                                          uint32_t b0, uint32_t b1) {
    asm volatile("mma.sync.aligned.m16n8k16.row.col.f32.f16.f16.f32 "
                 "{%0,%1,%2,%3}, {%4,%5,%6,%7}, {%8,%9}, {%0,%1,%2,%3};"
                 : "+f"(c0), "+f"(c1), "+f"(c2), "+f"(c3)
                 : "r"(a0), "r"(a1), "r"(a2), "r"(a3), "r"(b0), "r"(b1));
}

__device__ __forceinline__ float sigmoidf_fast(float x) {
    float e = __expf(-x);
    return __fdividef(1.0f, 1.0f + e);
}

__global__ void __launch_bounds__(256, 2)
gemm_sigmoid_kernel(float* __restrict__ out, int mtot) {
    extern __shared__ char smem[];
    const uint32_t sA = smem_u32(smem);
    const uint32_t sB = sA + SMEM_TILE;
    const int tid = threadIdx.x;
    const int wid = tid >> 5;
    const int lid = tid & 31;
    const int warp_m = wid & 3;    // 4 warps along M, 32 rows each
    const int warp_n = wid >> 2;   // 2 warps along N, 64 cols each

    const int arowbase = blockIdx.y * 128;   // output rows  (x rows)
    const int browbase = blockIdx.x * 128;   // output cols  (y rows)

    // ---- Fill SMEM: 128 rows x 16 chunks of 16B, per operand ----
    const uint4* gA = reinterpret_cast<const uint4*>(g_A) + (size_t)arowbase * 16;
    const uint4* gB = reinterpret_cast<const uint4*>(g_B) + (size_t)browbase * 16;
#pragma unroll
    for (int idx = tid; idx < 2048; idx += 256) {
        int row = idx >> 4;
        int c   = idx & 15;
        uint32_t off = (uint32_t)row * 256u + (uint32_t)((c ^ (row & 7)) << 4);
        *reinterpret_cast<uint4*>(smem + off)             = gA[idx];
        *reinterpret_cast<uint4*>(smem + SMEM_TILE + off) = gB[idx];
    }
    __syncthreads();

    // ---- Mainloop: K=128 = 8 k-steps of 16 ----
    float acc[2][8][4];
#pragma unroll
    for (int i = 0; i < 2; i++)
#pragma unroll
        for (int j = 0; j < 8; j++)
#pragma unroll
            for (int q = 0; q < 4; q++) acc[i][j][q] = 0.f;

    const int lane_lo = lid & 15;   // row within 16-row ldmatrix block
    const int lane_hi = lid >> 4;   // 0/1: 16B chunk-half select

    const int a_row0 = warp_m * 32 + lane_lo;        // + i*16
    const int b_row0 = warp_n * 64 + lane_lo;        // + jb*16

#pragma unroll
    for (int q = 0; q < 8; q++) {
        const int ch = q * 2 + lane_hi;              // chunk 0..15

        uint32_t a[2][4];
#pragma unroll
        for (int i = 0; i < 2; i++) {
            int row = a_row0 + i * 16;
            ldsm_x4(sA + (uint32_t)row * 256u + (uint32_t)((ch ^ (row & 7)) << 4),
                    a[i][0], a[i][1], a[i][2], a[i][3]);
        }

        uint32_t b[4][4];
#pragma unroll
        for (int jb = 0; jb < 4; jb++) {
            int row = b_row0 + jb * 16;
            ldsm_x4(sB + (uint32_t)row * 256u + (uint32_t)((ch ^ (row & 7)) << 4),
                    b[jb][0], b[jb][1], b[jb][2], b[jb][3]);
        }

#pragma unroll
        for (int i = 0; i < 2; i++)
#pragma unroll
            for (int j = 0; j < 8; j++) {
                int jb = j >> 1, sel = j & 1;
                mma_16816(acc[i][j][0], acc[i][j][1], acc[i][j][2], acc[i][j][3],
                          a[i][0], a[i][1], a[i][2], a[i][3],
                          b[jb][sel], b[jb][sel + 2]);
            }
    }

    // ---- Epilogue: sigmoid + coalesced float2 stores ----
    const int r_base = arowbase + warp_m * 32 + (lid >> 2);
    const int c_base = browbase + warp_n * 64 + ((lid & 3) << 1);
#pragma unroll
    for (int i = 0; i < 2; i++) {
        const int r0 = r_base + i * 16;
        float* p0 = out + (size_t)r0 * mtot + c_base;
        float* p1 = out + (size_t)(r0 + 8) * mtot + c_base;
#pragma unroll
        for (int j = 0; j < 8; j++) {
            float2 v0, v1;
            v0.x = sigmoidf_fast(acc[i][j][0]);
            v0.y = sigmoidf_fast(acc[i][j][1]);
            v1.x = sigmoidf_fast(acc[i][j][2]);
            v1.y = sigmoidf_fast(acc[i][j][3]);
            *reinterpret_cast<float2*>(p0 + j * 8) = v0;
            *reinterpret_cast<float2*>(p1 + j * 8) = v1;
        }
    }
}

// ---------------------------------------------------------------------------
// kernel_launch
// ---------------------------------------------------------------------------
extern "C" void kernel_launch(void* const* d_in, const int* in_sizes, int n_in,
                              void* d_out, int out_size) {
    const float* x = (const float*)d_in[0];   // [N, 128]
    const float* y = (const float*)d_in[1];   // [M, 128]
    const float* W = (const float*)d_in[2];   // [128, 128]
    float* out = (float*)d_out;

    const int N = in_sizes[0] / DDIM;   // 16384
    const int M = in_sizes[1] / DDIM;   // 16384

    cudaFuncSetAttribute(gemm_sigmoid_kernel,
                         cudaFuncAttributeMaxDynamicSharedMemorySize, SMEM_TOTAL);

    prep_x_kernel<<<N / 32, 128>>>(x, W);
    prep_y_kernel<<<(in_sizes[1] / 2 + 255) / 256, 256>>>(y, in_sizes[1] / 2);

    dim3 grid(M / 128, N / 128);
    gemm_sigmoid_kernel<<<grid, 256, SMEM_TOTAL>>>(out, M);
}

// round 11
// speedup vs baseline: 2.3727x; 1.0290x over previous
#include <cuda_runtime.h>
#include <cuda_fp16.h>
#include <cstdint>

// ============================================================================
// BilinearDiscriminator: out = sigmoid( (x @ W^T) @ y^T )
//   x: [16384, 128] f32, y: [16384, 128] f32, W: [128, 128] f32
//   out: [16384, 16384] f32
//
// R10 = R9 (fp16 single-product mma.sync GEMM, measured 357us / 3.68e-4)
//   + prep_x rewritten for FMA-roof (float4 LDS, 2 rows/iter, ILP-8)
//   + sigmoid via tanh.approx (1 MUFU instead of 2)
// ============================================================================

#define NROWS 16384
#define DDIM  128

static __device__ __align__(16) __half g_A[NROWS * DDIM];
static __device__ __align__(16) __half g_B[NROWS * DDIM];

// ---------------------------------------------------------------------------
// prep_x: Xt = x @ W^T in fp32, round to fp16 -> g_A
//   128 threads = one output column each; W row in float4 regs; 32 rows/block;
//   2 rows per inner pass -> 8 independent accumulators, 4 FMA per LDS.128.
// ---------------------------------------------------------------------------
__global__ void __launch_bounds__(128, 2)
prep_x_kernel(const float* __restrict__ x, const float* __restrict__ W) {
    __shared__ float4 Xs[32][32];          // 32 rows x 128 floats
    const int tid = threadIdx.x;           // output column d
    const int rowbase = blockIdx.x * 32;

    const float4* xv = reinterpret_cast<const float4*>(x) + (size_t)rowbase * 32;
    for (int i = tid; i < 32 * 32; i += 128)
        Xs[i >> 5][i & 31] = xv[i];

    float4 w[32];
    const float4* Wv = reinterpret_cast<const float4*>(W) + tid * 32;
#pragma unroll
    for (int k = 0; k < 32; k++) w[k] = Wv[k];
    __syncthreads();

#pragma unroll 1
    for (int r = 0; r < 32; r += 2) {
        float a0 = 0.f, a1 = 0.f, a2 = 0.f, a3 = 0.f;
        float b0 = 0.f, b1 = 0.f, b2 = 0.f, b3 = 0.f;
#pragma unroll
        for (int k = 0; k < 32; k++) {
            float4 xa = Xs[r][k];
            float4 xb = Xs[r + 1][k];
            a0 += w[k].x * xa.x; a1 += w[k].y * xa.y;
            a2 += w[k].z * xa.z; a3 += w[k].w * xa.w;
            b0 += w[k].x * xb.x; b1 += w[k].y * xb.y;
            b2 += w[k].z * xb.z; b3 += w[k].w * xb.w;
        }
        g_A[(size_t)(rowbase + r) * 128 + tid]     = __float2half((a0 + a1) + (a2 + a3));
        g_A[(size_t)(rowbase + r + 1) * 128 + tid] = __float2half((b0 + b1) + (b2 + b3));
    }
}

// ---------------------------------------------------------------------------
// prep_y: y fp32 -> fp16 (vectorized 2 elems/thread)
// ---------------------------------------------------------------------------
__global__ void __launch_bounds__(256)
prep_y_kernel(const float* __restrict__ y, int total2) {
    int i = blockIdx.x * blockDim.x + threadIdx.x;
    if (i >= total2) return;
    float2 v = reinterpret_cast<const float2*>(y)[i];
    __half2 h = __floats2half2_rn(v.x, v.y);
    reinterpret_cast<__half2*>(g_B)[i] = h;
}

// ---------------------------------------------------------------------------
// GEMM + sigmoid via mma.sync m16n8k16 fp16, K=128.
//   CTA tile: 128(M) x 128(N). 8 warps: warp_m = wid&3, warp_n = wid>>2.
//   SMEM per operand: 128 rows x 256B (16 x 16B chunks), chunk swizzle
//   phys_c = c ^ (row & 7) -> conflict-free STS and ldmatrix phases.
//   2 CTAs/SM so load/epilogue of one CTA overlaps the MMA of the other.
// ---------------------------------------------------------------------------
static constexpr int SMEM_TILE  = 128 * 256;       // 32 KB per operand
static constexpr int SMEM_TOTAL = 2 * SMEM_TILE;   // 64 KB

__device__ __forceinline__ uint32_t smem_u32(const void* p) {
    uint32_t a;
    asm("{ .reg .u64 t; cvta.to.shared.u64 t, %1; cvt.u32.u64 %0, t; }"
        : "=r"(a) : "l"(p));
    return a;
}

__device__ __forceinline__ void ldsm_x4(uint32_t addr, uint32_t& d0, uint32_t& d1,
                                        uint32_t& d2, uint32_t& d3) {
    asm volatile("ldmatrix.sync.aligned.m8n8.x4.shared.b16 {%0,%1,%2,%3}, [%4];"
                 : "=r"(d0), "=r"(d1), "=r"(d2), "=r"(d3) : "r"(addr));
}

__device__ __forceinline__ void mma_16816(float& c0, float& c1, float& c2, float& c3,
                                          uint32_t a0, uint32_t a1, uint32_t a2, uint32_t a3,
                                          uint32_t b0, uint32_t b1) {
    asm volatile("mma.sync.aligned.m16n8k16.row.col.f32.f16.f16.f32 "
                 "{%0,%1,%2,%3}, {%4,%5,%6,%7}, {%8,%9}, {%0,%1,%2,%3};"
                 : "+f"(c0), "+f"(c1), "+f"(c2), "+f"(c3)
                 : "r"(a0), "r"(a1), "r"(a2), "r"(a3), "r"(b0), "r"(b1));
}

// sigmoid(s) = 0.5*tanh(s/2) + 0.5 : one MUFU + FMA (vs ex2 + rcp).
__device__ __forceinline__ float sigmoid_tanh(float s) {
    float t;
    asm("tanh.approx.f32 %0, %1;" : "=f"(t) : "f"(s * 0.5f));
    return fmaf(t, 0.5f, 0.5f);
}

__global__ void __launch_bounds__(256, 2)
gemm_sigmoid_kernel(float* __restrict__ out, int mtot) {
    extern __shared__ char smem[];
    const uint32_t sA = smem_u32(smem);
    const uint32_t sB = sA + SMEM_TILE;
    const int tid = threadIdx.x;
    const int wid = tid >> 5;
    const int lid = tid & 31;
    const int warp_m = wid & 3;    // 4 warps along M, 32 rows each
    const int warp_n = wid >> 2;   // 2 warps along N, 64 cols each

    const int arowbase = blockIdx.y * 128;   // output rows  (x rows)
    const int browbase = blockIdx.x * 128;   // output cols  (y rows)

    // ---- Fill SMEM: 128 rows x 16 chunks of 16B, per operand ----
    const uint4* gA = reinterpret_cast<const uint4*>(g_A) + (size_t)arowbase * 16;
    const uint4* gB = reinterpret_cast<const uint4*>(g_B) + (size_t)browbase * 16;
#pragma unroll
    for (int idx = tid; idx < 2048; idx += 256) {
        int row = idx >> 4;
        int c   = idx & 15;
        uint32_t off = (uint32_t)row * 256u + (uint32_t)((c ^ (row & 7)) << 4);
        *reinterpret_cast<uint4*>(smem + off)             = gA[idx];
        *reinterpret_cast<uint4*>(smem + SMEM_TILE + off) = gB[idx];
    }
    __syncthreads();

    // ---- Mainloop: K=128 = 8 k-steps of 16 ----
    float acc[2][8][4];
#pragma unroll
    for (int i = 0; i < 2; i++)
#pragma unroll
        for (int j = 0; j < 8; j++)
#pragma unroll
            for (int q = 0; q < 4; q++) acc[i][j][q] = 0.f;

    const int lane_lo = lid & 15;   // row within 16-row ldmatrix block
    const int lane_hi = lid >> 4;   // 0/1: 16B chunk-half select

    const int a_row0 = warp_m * 32 + lane_lo;        // + i*16
    const int b_row0 = warp_n * 64 + lane_lo;        // + jb*16

#pragma unroll
    for (int q = 0; q < 8; q++) {
        const int ch = q * 2 + lane_hi;              // chunk 0..15

        uint32_t a[2][4];
#pragma unroll
        for (int i = 0; i < 2; i++) {
            int row = a_row0 + i * 16;
            ldsm_x4(sA + (uint32_t)row * 256u + (uint32_t)((ch ^ (row & 7)) << 4),
                    a[i][0], a[i][1], a[i][2], a[i][3]);
        }

        uint32_t b[4][4];
#pragma unroll
        for (int jb = 0; jb < 4; jb++) {
            int row = b_row0 + jb * 16;
            ldsm_x4(sB + (uint32_t)row * 256u + (uint32_t)((ch ^ (row & 7)) << 4),
                    b[jb][0], b[jb][1], b[jb][2], b[jb][3]);
        }

#pragma unroll
        for (int i = 0; i < 2; i++)
#pragma unroll
            for (int j = 0; j < 8; j++) {
                int jb = j >> 1, sel = j & 1;
                mma_16816(acc[i][j][0], acc[i][j][1], acc[i][j][2], acc[i][j][3],
                          a[i][0], a[i][1], a[i][2], a[i][3],
                          b[jb][sel], b[jb][sel + 2]);
            }
    }

    // ---- Epilogue: sigmoid (tanh.approx) + coalesced float2 stores ----
    const int r_base = arowbase + warp_m * 32 + (lid >> 2);
    const int c_base = browbase + warp_n * 64 + ((lid & 3) << 1);
#pragma unroll
    for (int i = 0; i < 2; i++) {
        const int r0 = r_base + i * 16;
        float* p0 = out + (size_t)r0 * mtot + c_base;
        float* p1 = out + (size_t)(r0 + 8) * mtot + c_base;
#pragma unroll
        for (int j = 0; j < 8; j++) {
            float2 v0, v1;
            v0.x = sigmoid_tanh(acc[i][j][0]);
            v0.y = sigmoid_tanh(acc[i][j][1]);
            v1.x = sigmoid_tanh(acc[i][j][2]);
            v1.y = sigmoid_tanh(acc[i][j][3]);
            *reinterpret_cast<float2*>(p0 + j * 8) = v0;
            *reinterpret_cast<float2*>(p1 + j * 8) = v1;
        }
    }
}

// ---------------------------------------------------------------------------
// kernel_launch
// ---------------------------------------------------------------------------
extern "C" void kernel_launch(void* const* d_in, const int* in_sizes, int n_in,
                              void* d_out, int out_size) {
    const float* x = (const float*)d_in[0];   // [N, 128]
    const float* y = (const float*)d_in[1];   // [M, 128]
    const float* W = (const float*)d_in[2];   // [128, 128]
    float* out = (float*)d_out;

    const int N = in_sizes[0] / DDIM;   // 16384
    const int M = in_sizes[1] / DDIM;   // 16384

    cudaFuncSetAttribute(gemm_sigmoid_kernel,
                         cudaFuncAttributeMaxDynamicSharedMemorySize, SMEM_TOTAL);

    prep_x_kernel<<<N / 32, 128>>>(x, W);
    prep_y_kernel<<<(in_sizes[1] / 2 + 255) / 256, 256>>>(y, in_sizes[1] / 2);

    dim3 grid(M / 128, N / 128);
    gemm_sigmoid_kernel<<<grid, 256, SMEM_TOTAL>>>(out, M);
}

// round 12
// speedup vs baseline: 2.4064x; 1.0142x over previous
#include <cuda_runtime.h>
#include <cuda_fp16.h>
#include <cstdint>

// ============================================================================
// BilinearDiscriminator: out = sigmoid( (x @ W^T) @ y^T )
//   x: [16384, 128] f32, y: [16384, 128] f32, W: [128, 128] f32
//   out: [16384, 16384] f32
//
// R12 = R11 GEMM (fp16 single-product mma.sync, 86% of measured mma.sync roof)
//   + prep fused into ONE kernel:
//       blocks [0,512):   Xt = 0.5 * (x @ W^T) -> fp16 g_A   (split-K, 16
//                         warps/SM instead of 8: W half-row per thread)
//       blocks [512,640): y fp32 -> fp16 g_B (grid-stride)
//   + epilogue: s already pre-scaled by 0.5 -> sigmoid = fma(tanh(s),.5,.5)
// ============================================================================

#define NROWS 16384
#define DDIM  128

static __device__ __align__(16) __half g_A[NROWS * DDIM];
static __device__ __align__(16) __half g_B[NROWS * DDIM];

// ---------------------------------------------------------------------------
// Fused prep kernel.
//   x-part: 512 blocks, 32 rows each. Thread (half=tid>>7, d=tid&127) owns
//   K-range [64*half, 64*half+64) of output column d -> float4 w[16] (64 regs,
//   not 128): ~95 regs total -> 16 warps/SM. Pair-reduce via smem.
//   y-part: 128 blocks, half2 conversion, grid-stride.
// ---------------------------------------------------------------------------
__global__ void __launch_bounds__(256, 2)
prep_kernel(const float* __restrict__ x, const float* __restrict__ y,
            const float* __restrict__ W, int xblocks, int total2) {
    __shared__ float4 Xs[32][32];       // 32 rows x 128 floats
    __shared__ float  red[2][256];

    if ((int)blockIdx.x < xblocks) {
        const int tid  = threadIdx.x;
        const int d    = tid & 127;
        const int half = tid >> 7;
        const int rowbase = blockIdx.x * 32;

        const float4* xv = reinterpret_cast<const float4*>(x) + (size_t)rowbase * 32;
        for (int i = tid; i < 32 * 32; i += 256)
            Xs[i >> 5][i & 31] = xv[i];

        float4 w[16];
        const float4* Wv = reinterpret_cast<const float4*>(W) + d * 32 + half * 16;
#pragma unroll
        for (int k = 0; k < 16; k++) w[k] = Wv[k];
        __syncthreads();

#pragma unroll 1
        for (int r = 0; r < 32; r += 2) {
            const float4* xa = &Xs[r][half * 16];
            const float4* xb = &Xs[r + 1][half * 16];
            float a0 = 0.f, a1 = 0.f, a2 = 0.f, a3 = 0.f;
            float b0 = 0.f, b1 = 0.f, b2 = 0.f, b3 = 0.f;
#pragma unroll
            for (int k = 0; k < 16; k++) {
                float4 va = xa[k];
                float4 vb = xb[k];
                a0 += w[k].x * va.x; a1 += w[k].y * va.y;
                a2 += w[k].z * va.z; a3 += w[k].w * va.w;
                b0 += w[k].x * vb.x; b1 += w[k].y * vb.y;
                b2 += w[k].z * vb.z; b3 += w[k].w * vb.w;
            }
            red[0][tid] = (a0 + a1) + (a2 + a3);
            red[1][tid] = (b0 + b1) + (b2 + b3);
            __syncthreads();
            if (tid < 128) {
                float sa = red[0][tid] + red[0][tid + 128];
                float sb = red[1][tid] + red[1][tid + 128];
                // pre-scale by 0.5: folds sigmoid's s*0.5 into the GEMM operand
                g_A[(size_t)(rowbase + r) * 128 + tid]     = __float2half(0.5f * sa);
                g_A[(size_t)(rowbase + r + 1) * 128 + tid] = __float2half(0.5f * sb);
            }
            __syncthreads();
        }
    } else {
        // y-part: fp32 -> fp16, 2 elems/thread/iter, grid-stride over 128 blocks
        const int yb = blockIdx.x - xblocks;
        const int stride = 128 * 256;
        for (int i = yb * 256 + threadIdx.x; i < total2; i += stride) {
            float2 v = reinterpret_cast<const float2*>(y)[i];
            reinterpret_cast<__half2*>(g_B)[i] = __floats2half2_rn(v.x, v.y);
        }
    }
}

// ---------------------------------------------------------------------------
// GEMM + sigmoid via mma.sync m16n8k16 fp16, K=128.
//   CTA tile: 128(M) x 128(N). 8 warps: warp_m = wid&3, warp_n = wid>>2.
//   SMEM per operand: 128 rows x 256B (16 x 16B chunks), chunk swizzle
//   phys_c = c ^ (row & 7) -> conflict-free STS and ldmatrix phases.
//   2 CTAs/SM so load/epilogue of one CTA overlaps the MMA of the other.
// ---------------------------------------------------------------------------
static constexpr int SMEM_TILE  = 128 * 256;       // 32 KB per operand
static constexpr int SMEM_TOTAL = 2 * SMEM_TILE;   // 64 KB

__device__ __forceinline__ uint32_t smem_u32(const void* p) {
    uint32_t a;
    asm("{ .reg .u64 t; cvta.to.shared.u64 t, %1; cvt.u32.u64 %0, t; }"
        : "=r"(a) : "l"(p));
    return a;
}

__device__ __forceinline__ void ldsm_x4(uint32_t addr, uint32_t& d0, uint32_t& d1,
                                        uint32_t& d2, uint32_t& d3) {
    asm volatile("ldmatrix.sync.aligned.m8n8.x4.shared.b16 {%0,%1,%2,%3}, [%4];"
                 : "=r"(d0), "=r"(d1), "=r"(d2), "=r"(d3) : "r"(addr));
}

__device__ __forceinline__ void mma_16816(float& c0, float& c1, float& c2, float& c3,
                                          uint32_t a0, uint32_t a1, uint32_t a2, uint32_t a3,
                                          uint32_t b0, uint32_t b1) {
    asm volatile("mma.sync.aligned.m16n8k16.row.col.f32.f16.f16.f32 "
                 "{%0,%1,%2,%3}, {%4,%5,%6,%7}, {%8,%9}, {%0,%1,%2,%3};"
                 : "+f"(c0), "+f"(c1), "+f"(c2), "+f"(c3)
                 : "r"(a0), "r"(a1), "r"(a2), "r"(a3), "r"(b0), "r"(b1));
}

// s is PRE-SCALED (score/2): sigmoid = 0.5*tanh(s) + 0.5, one MUFU + one FMA.
__device__ __forceinline__ float sigmoid_prescaled(float s) {
    float t;
    asm("tanh.approx.f32 %0, %1;" : "=f"(t) : "f"(s));
    return fmaf(t, 0.5f, 0.5f);
}

__global__ void __launch_bounds__(256, 2)
gemm_sigmoid_kernel(float* __restrict__ out, int mtot) {
    extern __shared__ char smem[];
    const uint32_t sA = smem_u32(smem);
    const uint32_t sB = sA + SMEM_TILE;
    const int tid = threadIdx.x;
    const int wid = tid >> 5;
    const int lid = tid & 31;
    const int warp_m = wid & 3;    // 4 warps along M, 32 rows each
    const int warp_n = wid >> 2;   // 2 warps along N, 64 cols each

    const int arowbase = blockIdx.y * 128;   // output rows  (x rows)
    const int browbase = blockIdx.x * 128;   // output cols  (y rows)

    // ---- Fill SMEM: 128 rows x 16 chunks of 16B, per operand ----
    const uint4* gA = reinterpret_cast<const uint4*>(g_A) + (size_t)arowbase * 16;
    const uint4* gB = reinterpret_cast<const uint4*>(g_B) + (size_t)browbase * 16;
#pragma unroll
    for (int idx = tid; idx < 2048; idx += 256) {
        int row = idx >> 4;
        int c   = idx & 15;
        uint32_t off = (uint32_t)row * 256u + (uint32_t)((c ^ (row & 7)) << 4);
        *reinterpret_cast<uint4*>(smem + off)             = gA[idx];
        *reinterpret_cast<uint4*>(smem + SMEM_TILE + off) = gB[idx];
    }
    __syncthreads();

    // ---- Mainloop: K=128 = 8 k-steps of 16 ----
    float acc[2][8][4];
#pragma unroll
    for (int i = 0; i < 2; i++)
#pragma unroll
        for (int j = 0; j < 8; j++)
#pragma unroll
            for (int q = 0; q < 4; q++) acc[i][j][q] = 0.f;

    const int lane_lo = lid & 15;   // row within 16-row ldmatrix block
    const int lane_hi = lid >> 4;   // 0/1: 16B chunk-half select

    const int a_row0 = warp_m * 32 + lane_lo;        // + i*16
    const int b_row0 = warp_n * 64 + lane_lo;        // + jb*16

#pragma unroll
    for (int q = 0; q < 8; q++) {
        const int ch = q * 2 + lane_hi;              // chunk 0..15

        uint32_t a[2][4];
#pragma unroll
        for (int i = 0; i < 2; i++) {
            int row = a_row0 + i * 16;
            ldsm_x4(sA + (uint32_t)row * 256u + (uint32_t)((ch ^ (row & 7)) << 4),
                    a[i][0], a[i][1], a[i][2], a[i][3]);
        }

        uint32_t b[4][4];
#pragma unroll
        for (int jb = 0; jb < 4; jb++) {
            int row = b_row0 + jb * 16;
            ldsm_x4(sB + (uint32_t)row * 256u + (uint32_t)((ch ^ (row & 7)) << 4),
                    b[jb][0], b[jb][1], b[jb][2], b[jb][3]);
        }

#pragma unroll
        for (int i = 0; i < 2; i++)
#pragma unroll
            for (int j = 0; j < 8; j++) {
                int jb = j >> 1, sel = j & 1;
                mma_16816(acc[i][j][0], acc[i][j][1], acc[i][j][2], acc[i][j][3],
                          a[i][0], a[i][1], a[i][2], a[i][3],
                          b[jb][sel], b[jb][sel + 2]);
            }
    }

    // ---- Epilogue: sigmoid (tanh.approx, pre-scaled) + float2 stores ----
    const int r_base = arowbase + warp_m * 32 + (lid >> 2);
    const int c_base = browbase + warp_n * 64 + ((lid & 3) << 1);
#pragma unroll
    for (int i = 0; i < 2; i++) {
        const int r0 = r_base + i * 16;
        float* p0 = out + (size_t)r0 * mtot + c_base;
        float* p1 = out + (size_t)(r0 + 8) * mtot + c_base;
#pragma unroll
        for (int j = 0; j < 8; j++) {
            float2 v0, v1;
            v0.x = sigmoid_prescaled(acc[i][j][0]);
            v0.y = sigmoid_prescaled(acc[i][j][1]);
            v1.x = sigmoid_prescaled(acc[i][j][2]);
            v1.y = sigmoid_prescaled(acc[i][j][3]);
            *reinterpret_cast<float2*>(p0 + j * 8) = v0;
            *reinterpret_cast<float2*>(p1 + j * 8) = v1;
        }
    }
}

// ---------------------------------------------------------------------------
// kernel_launch
// ---------------------------------------------------------------------------
extern "C" void kernel_launch(void* const* d_in, const int* in_sizes, int n_in,
                              void* d_out, int out_size) {
    const float* x = (const float*)d_in[0];   // [N, 128]
    const float* y = (const float*)d_in[1];   // [M, 128]
    const float* W = (const float*)d_in[2];   // [128, 128]
    float* out = (float*)d_out;

    const int N = in_sizes[0] / DDIM;   // 16384
    const int M = in_sizes[1] / DDIM;   // 16384

    cudaFuncSetAttribute(gemm_sigmoid_kernel,
                         cudaFuncAttributeMaxDynamicSharedMemorySize, SMEM_TOTAL);

    const int xblocks = N / 32;                 // 512
    const int yblocks = 128;
    prep_kernel<<<xblocks + yblocks, 256>>>(x, y, W, xblocks, in_sizes[1] / 2);

    dim3 grid(M / 128, N / 128);
    gemm_sigmoid_kernel<<<grid, 256, SMEM_TOTAL>>>(out, M);
}